// round 6
// baseline (speedup 1.0000x reference)
#include <cuda_runtime.h>
#include <cstdint>

// PointPillars scatter, inverted as index-map + gather.
// B=4, C=64, H=512, W=512, P read from in_sizes.
//
// Init-free map: g_map holds (pid+1), 0 = empty. Zero-initialized at module
// load; gather self-cleans consumed cells so every graph replay starts from
// a clean map. scatter -> gather stream ordering guarantees the reset lands
// before the next replay's atomics.
#define B_ 4
#define C_ 64
#define H_ 512
#define W_ 512
#define HW_ (H_ * W_)        // 262144 = 2^18
#define BHW_ (B_ * HW_)      // 1048576

__device__ int g_map[BHW_];  // zero-initialized at load; 0 = empty

// ---------------------------------------------------------------------------
// Kernel 1: scatter (pid+1) per pillar. atomicMax => highest pillar index
// wins == the reference's sequential last-write-wins.
__global__ void __launch_bounds__(256) k_scatter_idx(const int* __restrict__ coords, int P) {
    int p = blockIdx.x * blockDim.x + threadIdx.x;
    if (p >= P) return;
    int4 c = __ldcs(reinterpret_cast<const int4*>(coords) + p);  // [b, z, y, x]
    int b = c.x, y = c.z, x = c.w;
    if ((unsigned)y < H_ && (unsigned)x < W_) {
        atomicMax(&g_map[(b * H_ + y) * W_ + x], p + 1);
    }
}

// ---------------------------------------------------------------------------
// Kernel 2: gather + self-clean, 4 threads per BEV cell (16 channels each).
//   blockDim = (128, 4): threadIdx.x spans consecutive cells (w-contiguous
//   -> coalesced stores), threadIdx.y selects the channel quarter.
// Per thread: 4x float4 = 64B contiguous slice of the feature row
// (streaming), 16 strided channel stores (streaming). Low register count
// (~30) -> high occupancy -> enough MLP to hide the random feature-read
// latency. q==0 resets the map entry after a block-wide barrier (all four
// quarters have read it by then).
__global__ void __launch_bounds__(512) k_gather(const float* __restrict__ feat,
                                                float* __restrict__ out) {
    int s = blockIdx.x * blockDim.x + threadIdx.x;   // 0 .. BHW_-1
    int q = threadIdx.y;                             // channel quarter 0..3
    int b  = s >> 18;            // / HW_
    int sp = s & (HW_ - 1);      // within-batch spatial index

    int v = g_map[s];

    float4 r[4];
    if (v > 0) {
        const float4* fp = reinterpret_cast<const float4*>(feat + (size_t)(v - 1) * C_) + q * 4;
#pragma unroll
        for (int i = 0; i < 4; i++) r[i] = __ldcs(fp + i);
    } else {
#pragma unroll
        for (int i = 0; i < 4; i++) r[i] = make_float4(0.f, 0.f, 0.f, 0.f);
    }

    // All quarters have consumed g_map[s]; now quarter 0 may reset it.
    __syncthreads();
    if (v > 0 && q == 0) g_map[s] = 0;   // self-clean for next graph replay

    float* op = out + (size_t)b * (C_ * HW_) + (size_t)(q * 16) * HW_ + sp;
#pragma unroll
    for (int i = 0; i < 4; i++) {
        __stcs(op + (size_t)(4 * i + 0) * HW_, r[i].x);
        __stcs(op + (size_t)(4 * i + 1) * HW_, r[i].y);
        __stcs(op + (size_t)(4 * i + 2) * HW_, r[i].z);
        __stcs(op + (size_t)(4 * i + 3) * HW_, r[i].w);
    }
}

// ---------------------------------------------------------------------------
extern "C" void kernel_launch(void* const* d_in, const int* in_sizes, int n_in,
                              void* d_out, int out_size) {
    const float* feat   = (const float*)d_in[0];   // [P, C] float32
    const int*   coords = (const int*)d_in[1];     // [P, 4] int32
    int P = in_sizes[1] / 4;

    k_scatter_idx<<<(P + 255) / 256, 256>>>(coords, P);
    dim3 gblk(128, 4);
    k_gather<<<BHW_ / 128, gblk>>>(feat, (float*)d_out);
}